// round 16
// baseline (speedup 1.0000x reference)
#include <cuda_runtime.h>
#include <cuda_fp16.h>
#include <math.h>
#include <stdint.h>

// ---------------------------------------------------------------------------
// Problem dims (fixed)
// ---------------------------------------------------------------------------
#define BB 4
#define TQ 1024
#define TK 1024
#define DD 1024
#define HH 16
#define DK 64
#define DV 64
#define MROWS (BB * TQ)          // 4096
#define BH (BB * HH)             // 64

// ---------------------------------------------------------------------------
// Scratch (device globals — no allocations allowed)
// ---------------------------------------------------------------------------
__device__ float g_x2 [MROWS * DD];
__device__ float g_h  [MROWS * DD];
// fp16 activation buffers
__device__ __half g_xh[MROWS * DD];    // ln1(x) / mln1(x2) reuse
__device__ __half g_yh[MROWS * DD];    // ln2(y) / mln2(h) reuse
__device__ __half g_ph[MROWS * DD];    // flash output
// all 6 transposed weights, fp16: [6][N=1024][K=1024]
__device__ __half g_bh6[6 * DD * DD];
// q/k/v fp16 (written directly by GEMM epilogue)
__device__ __half g_qh[MROWS * DD];
__device__ __half g_kh[MROWS * DD];
__device__ __half g_vh[MROWS * DD];

// ---------------------------------------------------------------------------
// PTX helpers (sm_80+ baseline features only)
// ---------------------------------------------------------------------------
__device__ __forceinline__ uint32_t smem_u32(const void* p) {
    uint32_t a;
    asm("{ .reg .u64 t; cvta.to.shared.u64 t, %1; cvt.u32.u64 %0, t; }" : "=r"(a) : "l"(p));
    return a;
}
__device__ __forceinline__ void cpasync16(uint32_t dst, const void* src) {
    asm volatile("cp.async.cg.shared.global [%0], [%1], 16;" :: "r"(dst), "l"(src) : "memory");
}
#define CP_COMMIT() asm volatile("cp.async.commit_group;" ::: "memory")
#define CP_WAIT(n)  asm volatile("cp.async.wait_group %0;" :: "n"(n) : "memory")

__device__ __forceinline__ void ldm4(uint32_t* r, uint32_t addr) {
    asm volatile("ldmatrix.sync.aligned.m8n8.x4.shared.b16 {%0,%1,%2,%3}, [%4];"
        : "=r"(r[0]), "=r"(r[1]), "=r"(r[2]), "=r"(r[3]) : "r"(addr));
}
__device__ __forceinline__ void ldm4t(uint32_t* r, uint32_t addr) {
    asm volatile("ldmatrix.sync.aligned.m8n8.x4.trans.shared.b16 {%0,%1,%2,%3}, [%4];"
        : "=r"(r[0]), "=r"(r[1]), "=r"(r[2]), "=r"(r[3]) : "r"(addr));
}
// fp16 mma, fp32 accumulate
__device__ __forceinline__ void mma16816h(float* d, const uint32_t* a, const uint32_t* b) {
    asm volatile("mma.sync.aligned.m16n8k16.row.col.f32.f16.f16.f32 "
        "{%0,%1,%2,%3}, {%4,%5,%6,%7}, {%8,%9}, {%0,%1,%2,%3};"
        : "+f"(d[0]), "+f"(d[1]), "+f"(d[2]), "+f"(d[3])
        : "r"(a[0]), "r"(a[1]), "r"(a[2]), "r"(a[3]), "r"(b[0]), "r"(b[1]));
}

// ---------------------------------------------------------------------------
// LayerNorm + ReLU -> single fp16
// ---------------------------------------------------------------------------
__device__ __forceinline__ void ln_relu_row(const float* __restrict__ in,
                                            const float* __restrict__ gamma,
                                            const float* __restrict__ beta,
                                            __half* __restrict__ out,
                                            int row, int tid) {
    const float* p = in + (size_t)row * DD + tid * 4;
    float4 xv = *(const float4*)p;

    float s  = xv.x + xv.y + xv.z + xv.w;
    float ss = xv.x*xv.x + xv.y*xv.y + xv.z*xv.z + xv.w*xv.w;
    #pragma unroll
    for (int off = 16; off > 0; off >>= 1) {
        s  += __shfl_xor_sync(0xffffffffu, s,  off);
        ss += __shfl_xor_sync(0xffffffffu, ss, off);
    }
    __shared__ float sbuf[8], ssbuf[8];
    __shared__ float smean, sinv;
    int lane = tid & 31, warp = tid >> 5;
    if (lane == 0) { sbuf[warp] = s; ssbuf[warp] = ss; }
    __syncthreads();
    if (tid == 0) {
        float ts = 0.f, tss = 0.f;
        #pragma unroll
        for (int i = 0; i < 8; i++) { ts += sbuf[i]; tss += ssbuf[i]; }
        float mean = ts * (1.0f / DD);
        float var  = tss * (1.0f / DD) - mean * mean;
        smean = mean;
        sinv  = rsqrtf(var + 1e-5f);
    }
    __syncthreads();
    float m = smean, inv = sinv;

    int c = tid * 4;
    float4 g4 = *(const float4*)(gamma + c);
    float4 b4 = *(const float4*)(beta  + c);
    float o0 = fmaxf(0.f, (xv.x - m) * inv * g4.x + b4.x);
    float o1 = fmaxf(0.f, (xv.y - m) * inv * g4.y + b4.y);
    float o2 = fmaxf(0.f, (xv.z - m) * inv * g4.z + b4.z);
    float o3 = fmaxf(0.f, (xv.w - m) * inv * g4.w + b4.w);

    size_t base = (size_t)row * DD + c;
    *(__half2*)(out + base)     = __floats2half2_rn(o0, o1);
    *(__half2*)(out + base + 2) = __floats2half2_rn(o2, o3);
}

__global__ void ln_relu_h_kernel(const float* __restrict__ in,
                                 const float* __restrict__ gamma,
                                 const float* __restrict__ beta,
                                 __half* __restrict__ out) {
    ln_relu_row(in, gamma, beta, out, blockIdx.x, threadIdx.x);
}

// Merged pre-norms: blocks [0,4096) -> ln1(x)->xh, [4096,8192) -> ln2(y)->yh
__global__ void ln_relu_h2_kernel(const float* __restrict__ x,
                                  const float* __restrict__ g1, const float* __restrict__ b1,
                                  __half* __restrict__ xh,
                                  const float* __restrict__ y,
                                  const float* __restrict__ g2, const float* __restrict__ b2,
                                  __half* __restrict__ yh) {
    int blk = blockIdx.x;
    if (blk < MROWS) ln_relu_row(x, g1, b1, xh, blk, threadIdx.x);
    else             ln_relu_row(y, g2, b2, yh, blk - MROWS, threadIdx.x);
}

// ---------------------------------------------------------------------------
// Batched transpose: 6 weights W[K,N] fp32 -> Wt [N,K] fp16, one launch.
// ---------------------------------------------------------------------------
__global__ void transpose6_kernel(const float* __restrict__ w0, const float* __restrict__ w1,
                                  const float* __restrict__ w2, const float* __restrict__ w3,
                                  const float* __restrict__ w4, const float* __restrict__ w5,
                                  __half* __restrict__ dst) {
    const float* ws[6] = {w0, w1, w2, w3, w4, w5};
    const float* W = ws[blockIdx.z];
    __half* hi = dst + (size_t)blockIdx.z * DD * DD;

    __shared__ float tile[32][33];
    int tx = threadIdx.x, ty = threadIdx.y;
    int n0 = blockIdx.x * 32, k0 = blockIdx.y * 32;
    #pragma unroll
    for (int i = 0; i < 4; i++) {
        int kr = ty + i * 8;
        tile[kr][tx] = W[(size_t)(k0 + kr) * DD + n0 + tx];
    }
    __syncthreads();
    #pragma unroll
    for (int i = 0; i < 4; i++) {
        int nr = ty + i * 8;
        hi[(size_t)(n0 + nr) * DD + k0 + tx] = __float2half_rn(tile[tx][nr]);
    }
}

// ---------------------------------------------------------------------------
// HMMA GEMM body (fp16, single-term): C = A @ B^T (+bias, +res)
// CTA 256x128, BK=128 (8 chunks), 2-stage, single sync per chunk,
// 16 warps (4M x 4N), wtile 64x32.  Rows are 256B in smem.
// ---------------------------------------------------------------------------
#define GT_STAGE 98304
#define GA_OFF(buf)  ((buf) * GT_STAGE)
#define GB_OFF(buf)  ((buf) * GT_STAGE + 65536)
#define GT_SMEM (2 * GT_STAGE)                  // 196608
#define GT_THREADS 512

struct GPtrs { const char *a, *b; };

__device__ __forceinline__ void gt_load_chunk(uint32_t sb, int buf,
                                              const GPtrs& g, int chunk, int tid) {
    size_t kbyte = (size_t)chunk * 256;          // 128 halves = 256 bytes
    {
        uint32_t base = sb + GA_OFF(buf);
        #pragma unroll
        for (int it = 0; it < 8; it++) {
            int idx = tid + it * GT_THREADS;     // 0..4095
            int r = idx >> 4;
            int j = idx & 15;
            uint32_t so = (uint32_t)(r * 256 + j * 16);
            uint32_t sw = so ^ ((so >> 4) & 0x70);
            cpasync16(base + sw, g.a + (size_t)r * 2048 + kbyte + j * 16);
        }
    }
    {
        uint32_t base = sb + GB_OFF(buf);
        #pragma unroll
        for (int it = 0; it < 4; it++) {
            int idx = tid + it * GT_THREADS;     // 0..2047
            int r = idx >> 4;
            int j = idx & 15;
            uint32_t so = (uint32_t)(r * 256 + j * 16);
            uint32_t sw = so ^ ((so >> 4) & 0x70);
            cpasync16(base + sw, g.b + (size_t)r * 2048 + kbyte + j * 16);
        }
    }
}

__device__ __forceinline__ void gemm_body(uint32_t sb,
        const __half* __restrict__ A, const __half* __restrict__ B,
        const float* __restrict__ bias, const float* __restrict__ res,
        float* __restrict__ C, __half* __restrict__ Ch,
        int m0, int n0) {
    int tid = threadIdx.x;
    int lane = tid & 31;
    int wid = tid >> 5;              // 0..15
    int wm = wid & 3;                // 0..3 (M, 64 rows each)
    int wn = wid >> 2;               // 0..3 (N, 32 cols each)

    GPtrs g;
    g.a = (const char*)(A + (size_t)m0 * DD);
    g.b = (const char*)(B + (size_t)n0 * DD);

    float acc[4][4][4];
    #pragma unroll
    for (int i = 0; i < 4; i++)
        #pragma unroll
        for (int j = 0; j < 4; j++)
            #pragma unroll
            for (int r = 0; r < 4; r++) acc[i][j][r] = 0.f;

    uint32_t aRow = (uint32_t)(wm * 64 + (lane & 15));
    uint32_t xorb = (uint32_t)((lane & 7) * 16);
    uint32_t aHi  = (uint32_t)(((lane >> 4) & 1) * 16);
    uint32_t bRow = (uint32_t)(wn * 32 + ((lane >> 4) & 1) * 8 + (lane & 7));
    uint32_t bHi  = (uint32_t)(((lane >> 3) & 1) * 16);

    gt_load_chunk(sb, 0, g, 0, tid);
    CP_COMMIT();

    #pragma unroll 1
    for (int c = 0; c < 8; c++) {
        int buf = c & 1;
        CP_WAIT(0);
        __syncthreads();
        if (c < 7) {
            gt_load_chunk(sb, buf ^ 1, g, c + 1, tid);
            CP_COMMIT();
        }

        uint32_t tA = sb + GA_OFF(buf);
        uint32_t tB = sb + GB_OFF(buf);

        #pragma unroll
        for (int ks = 0; ks < 8; ks++) {
            uint32_t ka = ((uint32_t)(ks * 32) + aHi) ^ xorb;
            uint32_t kb = ((uint32_t)(ks * 32) + bHi) ^ xorb;

            uint32_t Af[4][4], Bf[2][4];
            #pragma unroll
            for (int i = 0; i < 4; i++) {
                uint32_t ro = (aRow + 16 * i) * 256;
                ldm4(Af[i], tA + ro + ka);
            }
            #pragma unroll
            for (int jp = 0; jp < 2; jp++) {
                uint32_t ro = (bRow + 16 * jp) * 256;
                ldm4(Bf[jp], tB + ro + kb);
            }
            #pragma unroll
            for (int i = 0; i < 4; i++) {
                #pragma unroll
                for (int j = 0; j < 4; j++) {
                    mma16816h(acc[i][j], Af[i], &Bf[j >> 1][(j & 1) * 2]);
                }
            }
        }
    }

    int rbase = m0 + wm * 64 + (lane >> 2);
    int cbase = n0 + wn * 32 + (lane & 3) * 2;
    #pragma unroll
    for (int j = 0; j < 4; j++) {
        int cc = cbase + 8 * j;
        float2 b2 = *(const float2*)(bias + cc);
        #pragma unroll
        for (int i = 0; i < 4; i++) {
            int r = rbase + 16 * i;
            float2 o0 = {acc[i][j][0] + b2.x, acc[i][j][1] + b2.y};
            float2 o1 = {acc[i][j][2] + b2.x, acc[i][j][3] + b2.y};
            size_t off0 = (size_t)r * DD + cc;
            size_t off1 = (size_t)(r + 8) * DD + cc;
            if (Ch) {
                *(__half2*)(Ch + off0) = __floats2half2_rn(o0.x, o0.y);
                *(__half2*)(Ch + off1) = __floats2half2_rn(o1.x, o1.y);
            } else {
                if (res) {
                    float2 r0 = *(const float2*)(res + off0);
                    float2 r1 = *(const float2*)(res + off1);
                    o0.x += r0.x; o0.y += r0.y;
                    o1.x += r1.x; o1.y += r1.y;
                }
                *(float2*)(C + off0) = o0;
                *(float2*)(C + off1) = o1;
            }
        }
    }
}

__global__ void __launch_bounds__(GT_THREADS, 1)
gemm_hmma(const __half* __restrict__ A, const __half* __restrict__ B,
          const float* __restrict__ bias, const float* __restrict__ res,
          float* __restrict__ C, __half* __restrict__ Ch) {
    extern __shared__ char smem[];
    uint32_t sb = smem_u32(smem);
    gemm_body(sb, A, B, bias, res, C, Ch, blockIdx.y * 256, blockIdx.x * 128);
}

// Combined q/k/v projection: grid (8, 16, 3); z selects operand set.
__global__ void __launch_bounds__(GT_THREADS, 1)
gemm_hmma_qkv(const __half* __restrict__ Ax, const __half* __restrict__ Ay,
              const __half* __restrict__ Wt6,
              const float* __restrict__ qb, const float* __restrict__ kb,
              const float* __restrict__ vb,
              __half* __restrict__ qh, __half* __restrict__ kh,
              __half* __restrict__ vh) {
    extern __shared__ char smem[];
    uint32_t sb = smem_u32(smem);
    int z = blockIdx.z;
    const __half* A = (z == 0) ? Ax : Ay;
    const __half* B = Wt6 + (size_t)z * DD * DD;
    const float* bias = (z == 0) ? qb : (z == 1) ? kb : vb;
    __half* Ch = (z == 0) ? qh : (z == 1) ? kh : vh;
    gemm_body(sb, A, B, bias, nullptr, nullptr, Ch,
              blockIdx.y * 256, blockIdx.x * 128);
}

// ---------------------------------------------------------------------------
// Fused flash attention (single fp16 HMMA), NO-MAX softmax via EX2-direct:
// p = exp2(S * 0.125*log2e + mbias2) where mbias2 is the mask bias
// pre-multiplied by log2e (0 or -1.44e30 -> exp2 = 0, exact vs select).
// Mask bias stored quad-permuted so each thread reads 4 x LDS.128 per chunk.
// 256-row q-tile; each warp covers 32 q-rows (two 16-row fragment groups).
// Grid: (TQ/256 = 4, BH = 64), 256 threads. 2-stage 1-ahead, 1 sync/chunk.
// ---------------------------------------------------------------------------
#define FA_KBUF(buf) (32768 + (buf) * 16384)
#define FA_SMEM      (65536 + 512)
#define EXP2_SCALE 0.1803368801111244f         // 0.125 * log2(e)
#define MASK_NEG  -1.4426950e30f               // -1e30 * log2(e)

__global__ void __launch_bounds__(256, 1)
flash_kernel(const __half* __restrict__ Qh, const __half* __restrict__ Kh,
             const __half* __restrict__ Vh, const int* __restrict__ mask,
             __half* __restrict__ Oh) {
    extern __shared__ char smem[];
    uint32_t sb = smem_u32(smem);
    int tid = threadIdx.x;
    int lane = tid & 31, wid = tid >> 5;
    int qtile = blockIdx.x;
    int bh = blockIdx.y;
    int b = bh >> 4, h = bh & 15;

    size_t qrow0 = (size_t)b * TQ + (size_t)qtile * 256;
    size_t krow0 = (size_t)b * TK;
    uint32_t hbyte = (uint32_t)h * 128;

    uint32_t sQ = sb;
    float* mfbase = (float*)(smem + 65536);    // quad-permuted bias*log2e

    const char* gK = (const char*)Kh;
    const char* gV = (const char*)Vh;

    // writer permutation: key j -> [(j>>1)&3]*16 + (j>>3)*2 + (j&1)
    int mperm = ((tid >> 1) & 3) * 16 + (tid >> 3) * 2 + (tid & 1);

    // Prologue: Q tile (256 rows) + KV chunk 0 in one group; mask chunk 0.
    {
        const char* gq = (const char*)Qh;
        #pragma unroll
        for (int it = 0; it < 8; it++) {
            int idx = tid + it * 256;          // 0..2047
            int r = idx >> 3, c16 = (idx & 7) * 16;
            uint32_t so = (uint32_t)(r * 128 + c16);
            uint32_t sw = so ^ ((so >> 3) & 0x70);
            cpasync16(sQ + sw, gq + (qrow0 + r) * 2048 + hbyte + c16);
        }
        uint32_t base = sb + FA_KBUF(0);
        #pragma unroll
        for (int t = 0; t < 2; t++) {
            const char* src = t ? gV : gK;
            uint32_t tb = base + t * 8192;
            #pragma unroll
            for (int it = 0; it < 2; it++) {
                int idx = tid + it * 256;
                int r = idx >> 3, c16 = (idx & 7) * 16;
                uint32_t so = (uint32_t)(r * 128 + c16);
                uint32_t sw = so ^ ((so >> 3) & 0x70);
                cpasync16(tb + sw, src + (krow0 + r) * 2048 + hbyte + c16);
            }
        }
    }
    CP_COMMIT();
    if (tid < 64)
        mfbase[mperm] = mask[(size_t)b * TK + tid] ? 0.f : MASK_NEG;

    uint32_t xorb = (uint32_t)((lane & 7) * 16);
    uint32_t aHi  = (uint32_t)(((lane >> 4) & 1) * 16);
    uint32_t kRowBase = 8 * ((lane >> 4) & 1) + (lane & 7);
    uint32_t kColHalf = 16 * ((lane >> 3) & 1);
    uint32_t vRowBase = 8 * ((lane >> 3) & 1) + (lane & 7);
    uint32_t vColHalf = 16 * ((lane >> 4) & 1);

    float O[2][8][4];
    #pragma unroll
    for (int gp = 0; gp < 2; gp++)
        #pragma unroll
        for (int f = 0; f < 8; f++)
            #pragma unroll
            for (int r = 0; r < 4; r++) O[gp][f][r] = 0.f;
    float lsum[4] = {0.f, 0.f, 0.f, 0.f};      // [gp*2 + rowhalf]
    uint32_t QF[2][4][4];

    #pragma unroll 1
    for (int c = 0; c < 16; c++) {
        int buf = c & 1;
        CP_WAIT(0);
        __syncthreads();                 // chunk c ready; buf^1 free

        if (c < 15) {
            int T0 = (c + 1) * 64;
            uint32_t base = sb + FA_KBUF(buf ^ 1);
            #pragma unroll
            for (int t = 0; t < 2; t++) {
                const char* src = t ? gV : gK;
                uint32_t tb = base + t * 8192;
                #pragma unroll
                for (int it = 0; it < 2; it++) {
                    int idx = tid + it * 256;
                    int r = idx >> 3, c16 = (idx & 7) * 16;
                    uint32_t so = (uint32_t)(r * 128 + c16);
                    uint32_t sw = so ^ ((so >> 3) & 0x70);
                    cpasync16(tb + sw, src + (krow0 + T0 + r) * 2048 + hbyte + c16);
                }
            }
            CP_COMMIT();
            if (tid < 64)
                mfbase[(buf ^ 1) * 64 + mperm] =
                    mask[(size_t)b * TK + T0 + tid] ? 0.f : MASK_NEG;
        }

        if (c == 0) {
            #pragma unroll
            for (int gp = 0; gp < 2; gp++) {
                uint32_t row = (uint32_t)(wid * 32 + gp * 16 + (lane & 15));
                #pragma unroll
                for (int ks = 0; ks < 4; ks++) {
                    uint32_t col = ((uint32_t)(ks * 32) + aHi) ^ xorb;
                    ldm4(QF[gp][ks], sQ + row * 128 + col);
                }
            }
        }

        uint32_t sK = sb + FA_KBUF(buf);
        uint32_t sV = sK + 8192;

        // 16 contiguous bias floats for this thread's quad = 4 x LDS.128
        const float4* mf4 = (const float4*)(mfbase + buf * 64 + (lane & 3) * 16);
        float4 mrow[4];
        mrow[0] = mf4[0]; mrow[1] = mf4[1]; mrow[2] = mf4[2]; mrow[3] = mf4[3];

        // ---- S = Q K^T (both groups share each K fragment)
        float S[2][8][4];
        #pragma unroll
        for (int gp = 0; gp < 2; gp++)
            #pragma unroll
            for (int n = 0; n < 8; n++)
                #pragma unroll
                for (int r = 0; r < 4; r++) S[gp][n][r] = 0.f;

        #pragma unroll
        for (int ks = 0; ks < 4; ks++) {
            uint32_t col = ((uint32_t)(ks * 32) + kColHalf) ^ xorb;
            #pragma unroll
            for (int np = 0; np < 4; np++) {
                uint32_t KF[4];
                uint32_t ro = (np * 16 + kRowBase) * 128;
                ldm4(KF, sK + ro + col);
                #pragma unroll
                for (int gp = 0; gp < 2; gp++) {
                    mma16816h(S[gp][np*2],   QF[gp][ks], KF);
                    mma16816h(S[gp][np*2+1], QF[gp][ks], KF + 2);
                }
            }
        }

        // ---- p = exp2(S*c + mbias2); accumulate sums; pack to fp16
        uint32_t P[2][4][4];
        #pragma unroll
        for (int gp = 0; gp < 2; gp++) {
            #pragma unroll
            for (int n = 0; n < 8; n++) {
                float mb0 = (n & 1) ? mrow[n >> 1].z : mrow[n >> 1].x;
                float mb1 = (n & 1) ? mrow[n >> 1].w : mrow[n >> 1].y;
                float p0 = exp2f(fmaf(S[gp][n][0], EXP2_SCALE, mb0));
                float p1 = exp2f(fmaf(S[gp][n][1], EXP2_SCALE, mb1));
                float p2 = exp2f(fmaf(S[gp][n][2], EXP2_SCALE, mb0));
                float p3 = exp2f(fmaf(S[gp][n][3], EXP2_SCALE, mb1));
                lsum[gp*2]     += p0 + p1;
                lsum[gp*2 + 1] += p2 + p3;
                __half2 h01 = __floats2half2_rn(p0, p1);
                __half2 h23 = __floats2half2_rn(p2, p3);
                int kk = n >> 1, base = (n & 1) * 2;
                P[gp][kk][base]     = *(uint32_t*)&h01;
                P[gp][kk][base + 1] = *(uint32_t*)&h23;
            }
        }

        // ---- O += P V (both groups share each V fragment)
        #pragma unroll
        for (int ks = 0; ks < 4; ks++) {
            uint32_t ro = (ks * 16 + vRowBase) * 128;
            #pragma unroll
            for (int dp = 0; dp < 4; dp++) {
                uint32_t col = ((uint32_t)(dp * 32) + vColHalf) ^ xorb;
                uint32_t VF[4];
                ldm4t(VF, sV + ro + col);
                #pragma unroll
                for (int gp = 0; gp < 2; gp++) {
                    mma16816h(O[gp][dp*2],   P[gp][ks], VF);
                    mma16816h(O[gp][dp*2+1], P[gp][ks], VF + 2);
                }
            }
        }
    }

    // final row-sum reduction + normalize + store
    #pragma unroll
    for (int s = 0; s < 4; s++) {
        lsum[s] += __shfl_xor_sync(0xffffffffu, lsum[s], 1);
        lsum[s] += __shfl_xor_sync(0xffffffffu, lsum[s], 2);
    }
    int col0 = h * 64 + (lane & 3) * 2;
    #pragma unroll
    for (int gp = 0; gp < 2; gp++) {
        float rinv0 = 1.f / lsum[gp*2];
        float rinv1 = 1.f / lsum[gp*2 + 1];
        int grow = (int)qrow0 + wid * 32 + gp * 16 + (lane >> 2);
        #pragma unroll
        for (int f = 0; f < 8; f++) {
            int cc = col0 + 8 * f;
            size_t off0 = (size_t)grow * DD + cc;
            size_t off1 = (size_t)(grow + 8) * DD + cc;
            *(__half2*)(Oh + off0) =
                __floats2half2_rn(O[gp][f][0] * rinv0, O[gp][f][1] * rinv0);
            *(__half2*)(Oh + off1) =
                __floats2half2_rn(O[gp][f][2] * rinv1, O[gp][f][3] * rinv1);
        }
    }
}

// ---------------------------------------------------------------------------
// Launch
// ---------------------------------------------------------------------------
extern "C" void kernel_launch(void* const* d_in, const int* in_sizes, int n_in,
                              void* d_out, int out_size) {
    const float* x      = (const float*)d_in[0];
    const float* y      = (const float*)d_in[1];
    const int*   mask   = (const int*)d_in[2];
    const float* ln1_g  = (const float*)d_in[3];
    const float* ln1_b  = (const float*)d_in[4];
    const float* ln2_g  = (const float*)d_in[5];
    const float* ln2_b  = (const float*)d_in[6];
    const float* q_w    = (const float*)d_in[7];
    const float* q_b    = (const float*)d_in[8];
    const float* k_w    = (const float*)d_in[9];
    const float* k_b    = (const float*)d_in[10];
    const float* v_w    = (const float*)d_in[11];
    const float* v_b    = (const float*)d_in[12];
    const float* o_w    = (const float*)d_in[13];
    const float* o_b    = (const float*)d_in[14];
    const float* mln1_g = (const float*)d_in[15];
    const float* mln1_b = (const float*)d_in[16];
    const float* l1_w   = (const float*)d_in[17];
    const float* l1_b   = (const float*)d_in[18];
    const float* mln2_g = (const float*)d_in[19];
    const float* mln2_b = (const float*)d_in[20];
    const float* l2_w   = (const float*)d_in[21];
    const float* l2_b   = (const float*)d_in[22];
    float* out = (float*)d_out;

    float *x2, *hbuf;
    __half *xh, *yh, *ph, *bh6, *qh, *kh, *vh;
    cudaGetSymbolAddress((void**)&x2,   g_x2);
    cudaGetSymbolAddress((void**)&hbuf, g_h);
    cudaGetSymbolAddress((void**)&xh,   g_xh);
    cudaGetSymbolAddress((void**)&yh,   g_yh);
    cudaGetSymbolAddress((void**)&ph,   g_ph);
    cudaGetSymbolAddress((void**)&bh6,  g_bh6);
    cudaGetSymbolAddress((void**)&qh,   g_qh);
    cudaGetSymbolAddress((void**)&kh,   g_kh);
    cudaGetSymbolAddress((void**)&vh,   g_vh);

    cudaFuncSetAttribute(gemm_hmma, cudaFuncAttributeMaxDynamicSharedMemorySize, GT_SMEM);
    cudaFuncSetAttribute(gemm_hmma_qkv, cudaFuncAttributeMaxDynamicSharedMemorySize, GT_SMEM);
    cudaFuncSetAttribute(flash_kernel, cudaFuncAttributeMaxDynamicSharedMemorySize, FA_SMEM);

    const size_t WSZ = (size_t)DD * DD;
    __half* bo = bh6 + 3 * WSZ;
    __half* b1 = bh6 + 4 * WSZ;
    __half* b2 = bh6 + 5 * WSZ;

    dim3 gemmGrid(8, 16);                       // N/128, M/256 = 128 CTAs
    dim3 qkvGrid(8, 16, 3);                     // combined q/k/v = 384 CTAs
    dim3 t6Grid(32, 32, 6);
    dim3 tBlock(32, 8);

    // 0) all 6 weight transposes in one launch
    transpose6_kernel<<<t6Grid, tBlock>>>(q_w, k_w, v_w, o_w, l1_w, l2_w, bh6);

    // 1) merged pre-norms -> fp16
    ln_relu_h2_kernel<<<2 * MROWS, 256>>>(x, ln1_g, ln1_b, xh, y, ln2_g, ln2_b, yh);

    // 2) q/k/v projections in ONE launch -> fp16
    gemm_hmma_qkv<<<qkvGrid, GT_THREADS, GT_SMEM>>>(xh, yh, bh6, q_b, k_b, v_b,
                                                    qh, kh, vh);

    // 3) fused flash attention -> fp16
    flash_kernel<<<dim3(4, BH), 256, FA_SMEM>>>(qh, kh, vh, mask, ph);

    // 4) output proj + residual (fp32 out)
    gemm_hmma<<<gemmGrid, GT_THREADS, GT_SMEM>>>(ph, bo, o_b, x, x2, nullptr);

    // 5) MLP
    ln_relu_h_kernel<<<MROWS, 256>>>(x2, mln1_g, mln1_b, xh);
    gemm_hmma<<<gemmGrid, GT_THREADS, GT_SMEM>>>(xh, b1, l1_b, nullptr, hbuf, nullptr);

    ln_relu_h_kernel<<<MROWS, 256>>>(hbuf, mln2_g, mln2_b, yh);
    gemm_hmma<<<gemmGrid, GT_THREADS, GT_SMEM>>>(yh, b2, l2_b, nullptr, out, nullptr);
}

// round 17
// speedup vs baseline: 1.5081x; 1.5081x over previous
#include <cuda_runtime.h>
#include <cuda_fp16.h>
#include <math.h>
#include <stdint.h>

// ---------------------------------------------------------------------------
// Problem dims (fixed)
// ---------------------------------------------------------------------------
#define BB 4
#define TQ 1024
#define TK 1024
#define DD 1024
#define HH 16
#define DK 64
#define DV 64
#define MROWS (BB * TQ)          // 4096
#define BH (BB * HH)             // 64

// ---------------------------------------------------------------------------
// Scratch (device globals — no allocations allowed)
// ---------------------------------------------------------------------------
__device__ float g_x2 [MROWS * DD];
__device__ float g_h  [MROWS * DD];
// fp16 activation buffers
__device__ __half g_xh[MROWS * DD];    // ln1(x) / mln1(x2) reuse
__device__ __half g_yh[MROWS * DD];    // ln2(y) / mln2(h) reuse
__device__ __half g_ph[MROWS * DD];    // flash output
// all 6 transposed weights, fp16: [6][N=1024][K=1024]
__device__ __half g_bh6[6 * DD * DD];
// q/k/v fp16 (written directly by GEMM epilogue)
__device__ __half g_qh[MROWS * DD];
__device__ __half g_kh[MROWS * DD];
__device__ __half g_vh[MROWS * DD];

// ---------------------------------------------------------------------------
// PTX helpers (sm_80+ baseline features only)
// ---------------------------------------------------------------------------
__device__ __forceinline__ uint32_t smem_u32(const void* p) {
    uint32_t a;
    asm("{ .reg .u64 t; cvta.to.shared.u64 t, %1; cvt.u32.u64 %0, t; }" : "=r"(a) : "l"(p));
    return a;
}
__device__ __forceinline__ void cpasync16(uint32_t dst, const void* src) {
    asm volatile("cp.async.cg.shared.global [%0], [%1], 16;" :: "r"(dst), "l"(src) : "memory");
}
#define CP_COMMIT() asm volatile("cp.async.commit_group;" ::: "memory")
#define CP_WAIT(n)  asm volatile("cp.async.wait_group %0;" :: "n"(n) : "memory")

__device__ __forceinline__ void ldm4(uint32_t* r, uint32_t addr) {
    asm volatile("ldmatrix.sync.aligned.m8n8.x4.shared.b16 {%0,%1,%2,%3}, [%4];"
        : "=r"(r[0]), "=r"(r[1]), "=r"(r[2]), "=r"(r[3]) : "r"(addr));
}
__device__ __forceinline__ void ldm4t(uint32_t* r, uint32_t addr) {
    asm volatile("ldmatrix.sync.aligned.m8n8.x4.trans.shared.b16 {%0,%1,%2,%3}, [%4];"
        : "=r"(r[0]), "=r"(r[1]), "=r"(r[2]), "=r"(r[3]) : "r"(addr));
}
// fp16 mma, fp32 accumulate
__device__ __forceinline__ void mma16816h(float* d, const uint32_t* a, const uint32_t* b) {
    asm volatile("mma.sync.aligned.m16n8k16.row.col.f32.f16.f16.f32 "
        "{%0,%1,%2,%3}, {%4,%5,%6,%7}, {%8,%9}, {%0,%1,%2,%3};"
        : "+f"(d[0]), "+f"(d[1]), "+f"(d[2]), "+f"(d[3])
        : "r"(a[0]), "r"(a[1]), "r"(a[2]), "r"(a[3]), "r"(b[0]), "r"(b[1]));
}

// ---------------------------------------------------------------------------
// LayerNorm + ReLU -> single fp16
// ---------------------------------------------------------------------------
__device__ __forceinline__ void ln_relu_row(const float* __restrict__ in,
                                            const float* __restrict__ gamma,
                                            const float* __restrict__ beta,
                                            __half* __restrict__ out,
                                            int row, int tid) {
    const float* p = in + (size_t)row * DD + tid * 4;
    float4 xv = *(const float4*)p;

    float s  = xv.x + xv.y + xv.z + xv.w;
    float ss = xv.x*xv.x + xv.y*xv.y + xv.z*xv.z + xv.w*xv.w;
    #pragma unroll
    for (int off = 16; off > 0; off >>= 1) {
        s  += __shfl_xor_sync(0xffffffffu, s,  off);
        ss += __shfl_xor_sync(0xffffffffu, ss, off);
    }
    __shared__ float sbuf[8], ssbuf[8];
    __shared__ float smean, sinv;
    int lane = tid & 31, warp = tid >> 5;
    if (lane == 0) { sbuf[warp] = s; ssbuf[warp] = ss; }
    __syncthreads();
    if (tid == 0) {
        float ts = 0.f, tss = 0.f;
        #pragma unroll
        for (int i = 0; i < 8; i++) { ts += sbuf[i]; tss += ssbuf[i]; }
        float mean = ts * (1.0f / DD);
        float var  = tss * (1.0f / DD) - mean * mean;
        smean = mean;
        sinv  = rsqrtf(var + 1e-5f);
    }
    __syncthreads();
    float m = smean, inv = sinv;

    int c = tid * 4;
    float4 g4 = *(const float4*)(gamma + c);
    float4 b4 = *(const float4*)(beta  + c);
    float o0 = fmaxf(0.f, (xv.x - m) * inv * g4.x + b4.x);
    float o1 = fmaxf(0.f, (xv.y - m) * inv * g4.y + b4.y);
    float o2 = fmaxf(0.f, (xv.z - m) * inv * g4.z + b4.z);
    float o3 = fmaxf(0.f, (xv.w - m) * inv * g4.w + b4.w);

    size_t base = (size_t)row * DD + c;
    *(__half2*)(out + base)     = __floats2half2_rn(o0, o1);
    *(__half2*)(out + base + 2) = __floats2half2_rn(o2, o3);
}

__global__ void ln_relu_h_kernel(const float* __restrict__ in,
                                 const float* __restrict__ gamma,
                                 const float* __restrict__ beta,
                                 __half* __restrict__ out) {
    ln_relu_row(in, gamma, beta, out, blockIdx.x, threadIdx.x);
}

// Merged pre-norms: blocks [0,4096) -> ln1(x)->xh, [4096,8192) -> ln2(y)->yh
__global__ void ln_relu_h2_kernel(const float* __restrict__ x,
                                  const float* __restrict__ g1, const float* __restrict__ b1,
                                  __half* __restrict__ xh,
                                  const float* __restrict__ y,
                                  const float* __restrict__ g2, const float* __restrict__ b2,
                                  __half* __restrict__ yh) {
    int blk = blockIdx.x;
    if (blk < MROWS) ln_relu_row(x, g1, b1, xh, blk, threadIdx.x);
    else             ln_relu_row(y, g2, b2, yh, blk - MROWS, threadIdx.x);
}

// ---------------------------------------------------------------------------
// Batched transpose: 6 weights W[K,N] fp32 -> Wt [N,K] fp16, one launch.
// ---------------------------------------------------------------------------
__global__ void transpose6_kernel(const float* __restrict__ w0, const float* __restrict__ w1,
                                  const float* __restrict__ w2, const float* __restrict__ w3,
                                  const float* __restrict__ w4, const float* __restrict__ w5,
                                  __half* __restrict__ dst) {
    const float* ws[6] = {w0, w1, w2, w3, w4, w5};
    const float* W = ws[blockIdx.z];
    __half* hi = dst + (size_t)blockIdx.z * DD * DD;

    __shared__ float tile[32][33];
    int tx = threadIdx.x, ty = threadIdx.y;
    int n0 = blockIdx.x * 32, k0 = blockIdx.y * 32;
    #pragma unroll
    for (int i = 0; i < 4; i++) {
        int kr = ty + i * 8;
        tile[kr][tx] = W[(size_t)(k0 + kr) * DD + n0 + tx];
    }
    __syncthreads();
    #pragma unroll
    for (int i = 0; i < 4; i++) {
        int nr = ty + i * 8;
        hi[(size_t)(n0 + nr) * DD + k0 + tx] = __float2half_rn(tile[tx][nr]);
    }
}

// ---------------------------------------------------------------------------
// HMMA GEMM body (fp16, single-term): C = A @ B^T (+bias, +res)
// CTA 256x128, BK=128 (8 chunks), 2-stage, single sync per chunk,
// 16 warps (4M x 4N), wtile 64x32.  Rows are 256B in smem.
// ---------------------------------------------------------------------------
#define GT_STAGE 98304
#define GA_OFF(buf)  ((buf) * GT_STAGE)
#define GB_OFF(buf)  ((buf) * GT_STAGE + 65536)
#define GT_SMEM (2 * GT_STAGE)                  // 196608
#define GT_THREADS 512

struct GPtrs { const char *a, *b; };

__device__ __forceinline__ void gt_load_chunk(uint32_t sb, int buf,
                                              const GPtrs& g, int chunk, int tid) {
    size_t kbyte = (size_t)chunk * 256;          // 128 halves = 256 bytes
    {
        uint32_t base = sb + GA_OFF(buf);
        #pragma unroll
        for (int it = 0; it < 8; it++) {
            int idx = tid + it * GT_THREADS;     // 0..4095
            int r = idx >> 4;
            int j = idx & 15;
            uint32_t so = (uint32_t)(r * 256 + j * 16);
            uint32_t sw = so ^ ((so >> 4) & 0x70);
            cpasync16(base + sw, g.a + (size_t)r * 2048 + kbyte + j * 16);
        }
    }
    {
        uint32_t base = sb + GB_OFF(buf);
        #pragma unroll
        for (int it = 0; it < 4; it++) {
            int idx = tid + it * GT_THREADS;     // 0..2047
            int r = idx >> 4;
            int j = idx & 15;
            uint32_t so = (uint32_t)(r * 256 + j * 16);
            uint32_t sw = so ^ ((so >> 4) & 0x70);
            cpasync16(base + sw, g.b + (size_t)r * 2048 + kbyte + j * 16);
        }
    }
}

__device__ __forceinline__ void gemm_body(uint32_t sb,
        const __half* __restrict__ A, const __half* __restrict__ B,
        const float* __restrict__ bias, const float* __restrict__ res,
        float* __restrict__ C, __half* __restrict__ Ch,
        int m0, int n0) {
    int tid = threadIdx.x;
    int lane = tid & 31;
    int wid = tid >> 5;              // 0..15
    int wm = wid & 3;                // 0..3 (M, 64 rows each)
    int wn = wid >> 2;               // 0..3 (N, 32 cols each)

    GPtrs g;
    g.a = (const char*)(A + (size_t)m0 * DD);
    g.b = (const char*)(B + (size_t)n0 * DD);

    float acc[4][4][4];
    #pragma unroll
    for (int i = 0; i < 4; i++)
        #pragma unroll
        for (int j = 0; j < 4; j++)
            #pragma unroll
            for (int r = 0; r < 4; r++) acc[i][j][r] = 0.f;

    uint32_t aRow = (uint32_t)(wm * 64 + (lane & 15));
    uint32_t xorb = (uint32_t)((lane & 7) * 16);
    uint32_t aHi  = (uint32_t)(((lane >> 4) & 1) * 16);
    uint32_t bRow = (uint32_t)(wn * 32 + ((lane >> 4) & 1) * 8 + (lane & 7));
    uint32_t bHi  = (uint32_t)(((lane >> 3) & 1) * 16);

    gt_load_chunk(sb, 0, g, 0, tid);
    CP_COMMIT();

    #pragma unroll 1
    for (int c = 0; c < 8; c++) {
        int buf = c & 1;
        CP_WAIT(0);
        __syncthreads();
        if (c < 7) {
            gt_load_chunk(sb, buf ^ 1, g, c + 1, tid);
            CP_COMMIT();
        }

        uint32_t tA = sb + GA_OFF(buf);
        uint32_t tB = sb + GB_OFF(buf);

        #pragma unroll
        for (int ks = 0; ks < 8; ks++) {
            uint32_t ka = ((uint32_t)(ks * 32) + aHi) ^ xorb;
            uint32_t kb = ((uint32_t)(ks * 32) + bHi) ^ xorb;

            uint32_t Af[4][4], Bf[2][4];
            #pragma unroll
            for (int i = 0; i < 4; i++) {
                uint32_t ro = (aRow + 16 * i) * 256;
                ldm4(Af[i], tA + ro + ka);
            }
            #pragma unroll
            for (int jp = 0; jp < 2; jp++) {
                uint32_t ro = (bRow + 16 * jp) * 256;
                ldm4(Bf[jp], tB + ro + kb);
            }
            #pragma unroll
            for (int i = 0; i < 4; i++) {
                #pragma unroll
                for (int j = 0; j < 4; j++) {
                    mma16816h(acc[i][j], Af[i], &Bf[j >> 1][(j & 1) * 2]);
                }
            }
        }
    }

    int rbase = m0 + wm * 64 + (lane >> 2);
    int cbase = n0 + wn * 32 + (lane & 3) * 2;
    #pragma unroll
    for (int j = 0; j < 4; j++) {
        int cc = cbase + 8 * j;
        float2 b2 = *(const float2*)(bias + cc);
        #pragma unroll
        for (int i = 0; i < 4; i++) {
            int r = rbase + 16 * i;
            float2 o0 = {acc[i][j][0] + b2.x, acc[i][j][1] + b2.y};
            float2 o1 = {acc[i][j][2] + b2.x, acc[i][j][3] + b2.y};
            size_t off0 = (size_t)r * DD + cc;
            size_t off1 = (size_t)(r + 8) * DD + cc;
            if (Ch) {
                *(__half2*)(Ch + off0) = __floats2half2_rn(o0.x, o0.y);
                *(__half2*)(Ch + off1) = __floats2half2_rn(o1.x, o1.y);
            } else {
                if (res) {
                    float2 r0 = *(const float2*)(res + off0);
                    float2 r1 = *(const float2*)(res + off1);
                    o0.x += r0.x; o0.y += r0.y;
                    o1.x += r1.x; o1.y += r1.y;
                }
                *(float2*)(C + off0) = o0;
                *(float2*)(C + off1) = o1;
            }
        }
    }
}

__global__ void __launch_bounds__(GT_THREADS, 1)
gemm_hmma(const __half* __restrict__ A, const __half* __restrict__ B,
          const float* __restrict__ bias, const float* __restrict__ res,
          float* __restrict__ C, __half* __restrict__ Ch) {
    extern __shared__ char smem[];
    uint32_t sb = smem_u32(smem);
    gemm_body(sb, A, B, bias, res, C, Ch, blockIdx.y * 256, blockIdx.x * 128);
}

// Combined q/k/v projection: grid (8, 16, 3); z selects operand set.
__global__ void __launch_bounds__(GT_THREADS, 1)
gemm_hmma_qkv(const __half* __restrict__ Ax, const __half* __restrict__ Ay,
              const __half* __restrict__ Wt6,
              const float* __restrict__ qb, const float* __restrict__ kb,
              const float* __restrict__ vb,
              __half* __restrict__ qh, __half* __restrict__ kh,
              __half* __restrict__ vh) {
    extern __shared__ char smem[];
    uint32_t sb = smem_u32(smem);
    int z = blockIdx.z;
    const __half* A = (z == 0) ? Ax : Ay;
    const __half* B = Wt6 + (size_t)z * DD * DD;
    const float* bias = (z == 0) ? qb : (z == 1) ? kb : vb;
    __half* Ch = (z == 0) ? qh : (z == 1) ? kh : vh;
    gemm_body(sb, A, B, bias, nullptr, nullptr, Ch,
              blockIdx.y * 256, blockIdx.x * 128);
}

// ---------------------------------------------------------------------------
// Fused flash attention (single fp16 HMMA), NO-MAX softmax, 256-row q-tile.
// EX2-direct: p = exp2(S * 0.125*log2e + mbias2), mbias2 pre-scaled by log2e
// (0 or -1.44e30 -> exp2 = 0, exact vs select). Scalar mask loads (R15 layout).
// Each warp covers 32 q-rows (two 16-row fragment groups) so every K/V
// fragment feeds 4 mma. Grid: (TQ/256 = 4, BH = 64), 256 threads.
// ---------------------------------------------------------------------------
#define FA_KBUF(buf) (32768 + (buf) * 16384)
#define FA_SMEM      (65536 + 512)
#define EXP2_SCALE 0.1803368801111244f         // 0.125 * log2(e)
#define MASK_NEG  -1.4426950e30f               // -1e30 * log2(e)

__global__ void __launch_bounds__(256, 1)
flash_kernel(const __half* __restrict__ Qh, const __half* __restrict__ Kh,
             const __half* __restrict__ Vh, const int* __restrict__ mask,
             __half* __restrict__ Oh) {
    extern __shared__ char smem[];
    uint32_t sb = smem_u32(smem);
    int tid = threadIdx.x;
    int lane = tid & 31, wid = tid >> 5;
    int qtile = blockIdx.x;
    int bh = blockIdx.y;
    int b = bh >> 4, h = bh & 15;

    size_t qrow0 = (size_t)b * TQ + (size_t)qtile * 256;
    size_t krow0 = (size_t)b * TK;
    uint32_t hbyte = (uint32_t)h * 128;

    uint32_t sQ = sb;
    float* mfbase = (float*)(smem + 65536);    // additive bias pre-scaled by log2e

    const char* gK = (const char*)Kh;
    const char* gV = (const char*)Vh;

    // Prologue: Q tile (256 rows) + KV chunk 0 in one group; mask chunk 0.
    {
        const char* gq = (const char*)Qh;
        #pragma unroll
        for (int it = 0; it < 8; it++) {
            int idx = tid + it * 256;          // 0..2047
            int r = idx >> 3, c16 = (idx & 7) * 16;
            uint32_t so = (uint32_t)(r * 128 + c16);
            uint32_t sw = so ^ ((so >> 3) & 0x70);
            cpasync16(sQ + sw, gq + (qrow0 + r) * 2048 + hbyte + c16);
        }
        uint32_t base = sb + FA_KBUF(0);
        #pragma unroll
        for (int t = 0; t < 2; t++) {
            const char* src = t ? gV : gK;
            uint32_t tb = base + t * 8192;
            #pragma unroll
            for (int it = 0; it < 2; it++) {
                int idx = tid + it * 256;
                int r = idx >> 3, c16 = (idx & 7) * 16;
                uint32_t so = (uint32_t)(r * 128 + c16);
                uint32_t sw = so ^ ((so >> 3) & 0x70);
                cpasync16(tb + sw, src + (krow0 + r) * 2048 + hbyte + c16);
            }
        }
    }
    CP_COMMIT();
    if (tid < 64) mfbase[tid] = mask[(size_t)b * TK + tid] ? 0.f : MASK_NEG;

    uint32_t xorb = (uint32_t)((lane & 7) * 16);
    uint32_t aHi  = (uint32_t)(((lane >> 4) & 1) * 16);
    uint32_t kRowBase = 8 * ((lane >> 4) & 1) + (lane & 7);
    uint32_t kColHalf = 16 * ((lane >> 3) & 1);
    uint32_t vRowBase = 8 * ((lane >> 3) & 1) + (lane & 7);
    uint32_t vColHalf = 16 * ((lane >> 4) & 1);

    float O[2][8][4];
    #pragma unroll
    for (int gp = 0; gp < 2; gp++)
        #pragma unroll
        for (int f = 0; f < 8; f++)
            #pragma unroll
            for (int r = 0; r < 4; r++) O[gp][f][r] = 0.f;
    float lsum[4] = {0.f, 0.f, 0.f, 0.f};      // [gp*2 + rowhalf]
    uint32_t QF[2][4][4];

    #pragma unroll 1
    for (int c = 0; c < 16; c++) {
        int buf = c & 1;
        CP_WAIT(0);
        __syncthreads();                 // chunk c ready; buf^1 free

        if (c < 15) {
            int T0 = (c + 1) * 64;
            uint32_t base = sb + FA_KBUF(buf ^ 1);
            #pragma unroll
            for (int t = 0; t < 2; t++) {
                const char* src = t ? gV : gK;
                uint32_t tb = base + t * 8192;
                #pragma unroll
                for (int it = 0; it < 2; it++) {
                    int idx = tid + it * 256;
                    int r = idx >> 3, c16 = (idx & 7) * 16;
                    uint32_t so = (uint32_t)(r * 128 + c16);
                    uint32_t sw = so ^ ((so >> 3) & 0x70);
                    cpasync16(tb + sw, src + (krow0 + T0 + r) * 2048 + hbyte + c16);
                }
            }
            CP_COMMIT();
            if (tid < 64)
                mfbase[(buf ^ 1) * 64 + tid] =
                    mask[(size_t)b * TK + T0 + tid] ? 0.f : MASK_NEG;
        }

        if (c == 0) {
            #pragma unroll
            for (int gp = 0; gp < 2; gp++) {
                uint32_t row = (uint32_t)(wid * 32 + gp * 16 + (lane & 15));
                #pragma unroll
                for (int ks = 0; ks < 4; ks++) {
                    uint32_t col = ((uint32_t)(ks * 32) + aHi) ^ xorb;
                    ldm4(QF[gp][ks], sQ + row * 128 + col);
                }
            }
        }

        uint32_t sK = sb + FA_KBUF(buf);
        uint32_t sV = sK + 8192;
        const float* mf = mfbase + buf * 64;

        // ---- S = Q K^T (both groups share each K fragment)
        float S[2][8][4];
        #pragma unroll
        for (int gp = 0; gp < 2; gp++)
            #pragma unroll
            for (int n = 0; n < 8; n++)
                #pragma unroll
                for (int r = 0; r < 4; r++) S[gp][n][r] = 0.f;

        #pragma unroll
        for (int ks = 0; ks < 4; ks++) {
            uint32_t col = ((uint32_t)(ks * 32) + kColHalf) ^ xorb;
            #pragma unroll
            for (int np = 0; np < 4; np++) {
                uint32_t KF[4];
                uint32_t ro = (np * 16 + kRowBase) * 128;
                ldm4(KF, sK + ro + col);
                #pragma unroll
                for (int gp = 0; gp < 2; gp++) {
                    mma16816h(S[gp][np*2],   QF[gp][ks], KF);
                    mma16816h(S[gp][np*2+1], QF[gp][ks], KF + 2);
                }
            }
        }

        // ---- p = exp2(S*c + mbias2); accumulate sums; pack to fp16
        uint32_t P[2][4][4];
        #pragma unroll
        for (int gp = 0; gp < 2; gp++) {
            #pragma unroll
            for (int n = 0; n < 8; n++) {
                int j = 8 * n + (lane & 3) * 2;
                float mb0 = mf[j], mb1 = mf[j + 1];
                float p0 = exp2f(fmaf(S[gp][n][0], EXP2_SCALE, mb0));
                float p1 = exp2f(fmaf(S[gp][n][1], EXP2_SCALE, mb1));
                float p2 = exp2f(fmaf(S[gp][n][2], EXP2_SCALE, mb0));
                float p3 = exp2f(fmaf(S[gp][n][3], EXP2_SCALE, mb1));
                lsum[gp*2]     += p0 + p1;
                lsum[gp*2 + 1] += p2 + p3;
                __half2 h01 = __floats2half2_rn(p0, p1);
                __half2 h23 = __floats2half2_rn(p2, p3);
                int kk = n >> 1, base = (n & 1) * 2;
                P[gp][kk][base]     = *(uint32_t*)&h01;
                P[gp][kk][base + 1] = *(uint32_t*)&h23;
            }
        }

        // ---- O += P V (both groups share each V fragment)
        #pragma unroll
        for (int ks = 0; ks < 4; ks++) {
            uint32_t ro = (ks * 16 + vRowBase) * 128;
            #pragma unroll
            for (int dp = 0; dp < 4; dp++) {
                uint32_t col = ((uint32_t)(dp * 32) + vColHalf) ^ xorb;
                uint32_t VF[4];
                ldm4t(VF, sV + ro + col);
                #pragma unroll
                for (int gp = 0; gp < 2; gp++) {
                    mma16816h(O[gp][dp*2],   P[gp][ks], VF);
                    mma16816h(O[gp][dp*2+1], P[gp][ks], VF + 2);
                }
            }
        }
    }

    // final row-sum reduction + normalize + store
    #pragma unroll
    for (int s = 0; s < 4; s++) {
        lsum[s] += __shfl_xor_sync(0xffffffffu, lsum[s], 1);
        lsum[s] += __shfl_xor_sync(0xffffffffu, lsum[s], 2);
    }
    int col0 = h * 64 + (lane & 3) * 2;
    #pragma unroll
    for (int gp = 0; gp < 2; gp++) {
        float rinv0 = 1.f / lsum[gp*2];
        float rinv1 = 1.f / lsum[gp*2 + 1];
        int grow = (int)qrow0 + wid * 32 + gp * 16 + (lane >> 2);
        #pragma unroll
        for (int f = 0; f < 8; f++) {
            int cc = col0 + 8 * f;
            size_t off0 = (size_t)grow * DD + cc;
            size_t off1 = (size_t)(grow + 8) * DD + cc;
            *(__half2*)(Oh + off0) =
                __floats2half2_rn(O[gp][f][0] * rinv0, O[gp][f][1] * rinv0);
            *(__half2*)(Oh + off1) =
                __floats2half2_rn(O[gp][f][2] * rinv1, O[gp][f][3] * rinv1);
        }
    }
}

// ---------------------------------------------------------------------------
// Launch
// ---------------------------------------------------------------------------
extern "C" void kernel_launch(void* const* d_in, const int* in_sizes, int n_in,
                              void* d_out, int out_size) {
    const float* x      = (const float*)d_in[0];
    const float* y      = (const float*)d_in[1];
    const int*   mask   = (const int*)d_in[2];
    const float* ln1_g  = (const float*)d_in[3];
    const float* ln1_b  = (const float*)d_in[4];
    const float* ln2_g  = (const float*)d_in[5];
    const float* ln2_b  = (const float*)d_in[6];
    const float* q_w    = (const float*)d_in[7];
    const float* q_b    = (const float*)d_in[8];
    const float* k_w    = (const float*)d_in[9];
    const float* k_b    = (const float*)d_in[10];
    const float* v_w    = (const float*)d_in[11];
    const float* v_b    = (const float*)d_in[12];
    const float* o_w    = (const float*)d_in[13];
    const float* o_b    = (const float*)d_in[14];
    const float* mln1_g = (const float*)d_in[15];
    const float* mln1_b = (const float*)d_in[16];
    const float* l1_w   = (const float*)d_in[17];
    const float* l1_b   = (const float*)d_in[18];
    const float* mln2_g = (const float*)d_in[19];
    const float* mln2_b = (const float*)d_in[20];
    const float* l2_w   = (const float*)d_in[21];
    const float* l2_b   = (const float*)d_in[22];
    float* out = (float*)d_out;

    float *x2, *hbuf;
    __half *xh, *yh, *ph, *bh6, *qh, *kh, *vh;
    cudaGetSymbolAddress((void**)&x2,   g_x2);
    cudaGetSymbolAddress((void**)&hbuf, g_h);
    cudaGetSymbolAddress((void**)&xh,   g_xh);
    cudaGetSymbolAddress((void**)&yh,   g_yh);
    cudaGetSymbolAddress((void**)&ph,   g_ph);
    cudaGetSymbolAddress((void**)&bh6,  g_bh6);
    cudaGetSymbolAddress((void**)&qh,   g_qh);
    cudaGetSymbolAddress((void**)&kh,   g_kh);
    cudaGetSymbolAddress((void**)&vh,   g_vh);

    cudaFuncSetAttribute(gemm_hmma, cudaFuncAttributeMaxDynamicSharedMemorySize, GT_SMEM);
    cudaFuncSetAttribute(gemm_hmma_qkv, cudaFuncAttributeMaxDynamicSharedMemorySize, GT_SMEM);
    cudaFuncSetAttribute(flash_kernel, cudaFuncAttributeMaxDynamicSharedMemorySize, FA_SMEM);

    const size_t WSZ = (size_t)DD * DD;
    __half* bo = bh6 + 3 * WSZ;
    __half* b1 = bh6 + 4 * WSZ;
    __half* b2 = bh6 + 5 * WSZ;

    dim3 gemmGrid(8, 16);                       // N/128, M/256 = 128 CTAs
    dim3 qkvGrid(8, 16, 3);                     // combined q/k/v = 384 CTAs
    dim3 t6Grid(32, 32, 6);
    dim3 tBlock(32, 8);

    // 0) all 6 weight transposes in one launch
    transpose6_kernel<<<t6Grid, tBlock>>>(q_w, k_w, v_w, o_w, l1_w, l2_w, bh6);

    // 1) merged pre-norms -> fp16
    ln_relu_h2_kernel<<<2 * MROWS, 256>>>(x, ln1_g, ln1_b, xh, y, ln2_g, ln2_b, yh);

    // 2) q/k/v projections in ONE launch -> fp16
    gemm_hmma_qkv<<<qkvGrid, GT_THREADS, GT_SMEM>>>(xh, yh, bh6, q_b, k_b, v_b,
                                                    qh, kh, vh);

    // 3) fused flash attention -> fp16
    flash_kernel<<<dim3(4, BH), 256, FA_SMEM>>>(qh, kh, vh, mask, ph);

    // 4) output proj + residual (fp32 out)
    gemm_hmma<<<gemmGrid, GT_THREADS, GT_SMEM>>>(ph, bo, o_b, x, x2, nullptr);

    // 5) MLP
    ln_relu_h_kernel<<<MROWS, 256>>>(x2, mln1_g, mln1_b, xh);
    gemm_hmma<<<gemmGrid, GT_THREADS, GT_SMEM>>>(xh, b1, l1_b, nullptr, hbuf, nullptr);

    ln_relu_h_kernel<<<MROWS, 256>>>(hbuf, mln2_g, mln2_b, yh);
    gemm_hmma<<<gemmGrid, GT_THREADS, GT_SMEM>>>(yh, b2, l2_b, nullptr, out, nullptr);
}